// round 1
// baseline (speedup 1.0000x reference)
#include <cuda_runtime.h>

#define NN 50000
#define NE 800000
#define INC 128
#define HEADS 8
#define HID 16
#define H1DIM 128   // HEADS*HID
#define OUTC 40
#define NEG 0.2f

// ---------------- scratch (allocation-free: __device__ globals) ----------------
__device__ float g_h1[NN * H1DIM];     // layer1 linear output [N, 8, 16]
__device__ float g_as1[NN * HEADS];    // per-node src attention logits
__device__ float g_ad1[NN * HEADS];
__device__ float g_max1[NN * HEADS];   // segment max
__device__ float g_sum1[NN * HEADS];   // segment sum of exp
__device__ float g_out1[NN * H1DIM];   // layer1 aggregated (then ELU'd in place)
__device__ float g_h2[NN * OUTC];      // layer2 linear output
__device__ float g_as2[NN];
__device__ float g_ad2[NN];
__device__ float g_max2[NN];
__device__ float g_sum2[NN];
__device__ float g_e2[NE];             // layer2 per-edge exp numerator

__device__ __forceinline__ float leaky(float v) { return v > 0.f ? v : NEG * v; }

__device__ __forceinline__ void atomicMaxFloat(float* addr, float v) {
    if (v >= 0.f) atomicMax((int*)addr, __float_as_int(v));
    else          atomicMin((unsigned int*)addr, __float_as_uint(v));
}

__device__ __forceinline__ void redAddV4(float* p, float4 m) {
    asm volatile("red.global.add.v4.f32 [%0], {%1,%2,%3,%4};"
                 :: "l"(p), "f"(m.x), "f"(m.y), "f"(m.z), "f"(m.w) : "memory");
}

// ---------------- init: zeros, -inf maxes, d_out = bias ----------------
__global__ void k_init(const float* __restrict__ b2, float* __restrict__ dout) {
    int i = blockIdx.x * blockDim.x + threadIdx.x;
    int st = gridDim.x * blockDim.x;
    const float ninf = __int_as_float(0xff800000);
    for (int j = i; j < NN * H1DIM; j += st) g_out1[j] = 0.f;
    for (int j = i; j < NN * HEADS; j += st) { g_sum1[j] = 0.f; g_max1[j] = ninf; }
    for (int j = i; j < NN; j += st)         { g_sum2[j] = 0.f; g_max2[j] = ninf; }
    for (int j = i; j < NN * OUTC; j += st)  dout[j] = b2[j % OUTC];
}

// ---------------- GEMM1: g_h1 = x[NN,128] @ W1[128,128] ----------------
// BM=64, BN=128, BK=16, 256 threads, TM=8, TN=4
__global__ void k_gemm1(const float* __restrict__ A, const float* __restrict__ B) {
    __shared__ float As[16][64];
    __shared__ float Bs[16][128];
    int tid = threadIdx.x;
    int tx = tid & 31;          // col group: cols tx*4..+4
    int ty = tid >> 5;          // row group: rows ty*8..+8
    int row0 = blockIdx.x * 64;
    float acc[8][4] = {};
    for (int k0 = 0; k0 < 128; k0 += 16) {
        {   // A tile 64x16 -> transposed smem. 256 float4 loads.
            int r = tid >> 2;
            int kk = (tid & 3) * 4;
            int grow = row0 + r;
            float4 v = make_float4(0.f, 0.f, 0.f, 0.f);
            if (grow < NN) v = *(const float4*)&A[grow * 128 + k0 + kk];
            As[kk + 0][r] = v.x; As[kk + 1][r] = v.y;
            As[kk + 2][r] = v.z; As[kk + 3][r] = v.w;
        }
#pragma unroll
        for (int p = 0; p < 2; p++) {   // B tile 16x128 = 512 float4
            int fi = tid + p * 256;
            int kk = fi >> 5;
            int nc = (fi & 31) * 4;
            *(float4*)&Bs[kk][nc] = *(const float4*)&B[(k0 + kk) * 128 + nc];
        }
        __syncthreads();
#pragma unroll
        for (int kk = 0; kk < 16; kk++) {
            float a[8], b[4];
#pragma unroll
            for (int i = 0; i < 8; i++) a[i] = As[kk][ty * 8 + i];
#pragma unroll
            for (int j = 0; j < 4; j++) b[j] = Bs[kk][tx * 4 + j];
#pragma unroll
            for (int i = 0; i < 8; i++)
#pragma unroll
                for (int j = 0; j < 4; j++) acc[i][j] += a[i] * b[j];
        }
        __syncthreads();
    }
#pragma unroll
    for (int i = 0; i < 8; i++) {
        int grow = row0 + ty * 8 + i;
        if (grow < NN)
            *(float4*)&g_h1[grow * 128 + tx * 4] =
                make_float4(acc[i][0], acc[i][1], acc[i][2], acc[i][3]);
    }
}

// ---------------- per-node attention logits, layer 1 (warp/node) ----------------
__global__ void k_att1(const float* __restrict__ att_src, const float* __restrict__ att_dst) {
    int lane = threadIdx.x & 31;
    int warp = (blockIdx.x * blockDim.x + threadIdx.x) >> 5;
    int nwarp = (gridDim.x * blockDim.x) >> 5;
    float4 ws = *(const float4*)&att_src[lane * 4];
    float4 wd = *(const float4*)&att_dst[lane * 4];
    for (int n = warp; n < NN; n += nwarp) {
        float4 h = *(const float4*)&g_h1[n * 128 + lane * 4];
        float ps = h.x * ws.x + h.y * ws.y + h.z * ws.z + h.w * ws.w;
        float pd = h.x * wd.x + h.y * wd.y + h.z * wd.z + h.w * wd.w;
        ps += __shfl_xor_sync(0xffffffffu, ps, 1);
        ps += __shfl_xor_sync(0xffffffffu, ps, 2);
        pd += __shfl_xor_sync(0xffffffffu, pd, 1);
        pd += __shfl_xor_sync(0xffffffffu, pd, 2);
        if ((lane & 3) == 0) {
            g_as1[n * 8 + (lane >> 2)] = ps;
            g_ad1[n * 8 + (lane >> 2)] = pd;
        }
    }
}

// ---------------- layer1 edge pass A: segment max ----------------
__global__ void k_e1max(const int* __restrict__ ei) {
    int e = blockIdx.x * blockDim.x + threadIdx.x;
    if (e >= NE) return;
    int s = ei[e], d = ei[NE + e];
    float4 a0 = *(const float4*)&g_as1[s * 8];
    float4 a1 = *(const float4*)&g_as1[s * 8 + 4];
    float4 b0 = *(const float4*)&g_ad1[d * 8];
    float4 b1 = *(const float4*)&g_ad1[d * 8 + 4];
    float l[8] = {a0.x + b0.x, a0.y + b0.y, a0.z + b0.z, a0.w + b0.w,
                  a1.x + b1.x, a1.y + b1.y, a1.z + b1.z, a1.w + b1.w};
#pragma unroll
    for (int h = 0; h < 8; h++) atomicMaxFloat(&g_max1[d * 8 + h], leaky(l[h]));
}

// ---------------- layer1 edge pass B: segment sum of exp ----------------
__global__ void k_e1sum(const int* __restrict__ ei) {
    int e = blockIdx.x * blockDim.x + threadIdx.x;
    if (e >= NE) return;
    int s = ei[e], d = ei[NE + e];
    float4 a0 = *(const float4*)&g_as1[s * 8];
    float4 a1 = *(const float4*)&g_as1[s * 8 + 4];
    float4 b0 = *(const float4*)&g_ad1[d * 8];
    float4 b1 = *(const float4*)&g_ad1[d * 8 + 4];
    float4 m0 = *(const float4*)&g_max1[d * 8];
    float4 m1 = *(const float4*)&g_max1[d * 8 + 4];
    float l[8] = {a0.x + b0.x, a0.y + b0.y, a0.z + b0.z, a0.w + b0.w,
                  a1.x + b1.x, a1.y + b1.y, a1.z + b1.z, a1.w + b1.w};
    float m[8] = {m0.x, m0.y, m0.z, m0.w, m1.x, m1.y, m1.z, m1.w};
#pragma unroll
    for (int h = 0; h < 8; h++)
        atomicAdd(&g_sum1[d * 8 + h], __expf(leaky(l[h]) - m[h]));
}

// ---------------- layer1 edge pass C: weighted aggregation (warp/edge) ----------------
__global__ void k_e1agg(const int* __restrict__ ei) {
    int lane = threadIdx.x & 31;
    int warp = (blockIdx.x * blockDim.x + threadIdx.x) >> 5;
    int nwarp = (gridDim.x * blockDim.x) >> 5;
    for (int e = warp; e < NE; e += nwarp) {
        int s = ei[e], d = ei[NE + e];
        float alpha = 0.f;
        if (lane < 8) {
            float logit = leaky(g_as1[s * 8 + lane] + g_ad1[d * 8 + lane]);
            alpha = __expf(logit - g_max1[d * 8 + lane]) / g_sum1[d * 8 + lane];
        }
        float a = __shfl_sync(0xffffffffu, alpha, lane >> 2);  // head = lane/4
        float4 h = *(const float4*)&g_h1[s * 128 + lane * 4];
        redAddV4(&g_out1[d * 128 + lane * 4],
                 make_float4(h.x * a, h.y * a, h.z * a, h.w * a));
    }
}

// ---------------- bias + ELU, in place on g_out1 ----------------
__global__ void k_act1(const float* __restrict__ b1) {
    int st = gridDim.x * blockDim.x;
    for (int i = blockIdx.x * blockDim.x + threadIdx.x; i < NN * H1DIM; i += st) {
        float v = g_out1[i] + b1[i & 127];
        g_out1[i] = v > 0.f ? v : expm1f(v);
    }
}

// ---------------- GEMM2: g_h2 = g_out1[NN,128] @ W2[128,40] ----------------
// BM=128, BK=16, 256 threads, TM=4 (rows), TN=5 (cols)
__global__ void k_gemm2(const float* __restrict__ B) {
    __shared__ float As[16][128];
    __shared__ float Bs[16][40];
    int tid = threadIdx.x;
    int tx = tid & 7;           // col group: cols tx*5..+5
    int ty = tid >> 3;          // row group: rows ty*4..+4
    int row0 = blockIdx.x * 128;
    float acc[4][5] = {};
    for (int k0 = 0; k0 < 128; k0 += 16) {
#pragma unroll
        for (int p = 0; p < 2; p++) {   // A tile 128x16 = 512 float4
            int fi = tid + p * 256;
            int r = fi >> 2;
            int kk = (fi & 3) * 4;
            int grow = row0 + r;
            float4 v = make_float4(0.f, 0.f, 0.f, 0.f);
            if (grow < NN) v = *(const float4*)&g_out1[grow * 128 + k0 + kk];
            As[kk + 0][r] = v.x; As[kk + 1][r] = v.y;
            As[kk + 2][r] = v.z; As[kk + 3][r] = v.w;
        }
        if (tid < 160) {                // B tile 16x40 = 160 float4
            int kk = tid / 10;
            int nc = (tid % 10) * 4;
            *(float4*)&Bs[kk][nc] = *(const float4*)&B[(k0 + kk) * 40 + nc];
        }
        __syncthreads();
#pragma unroll
        for (int kk = 0; kk < 16; kk++) {
            float a[4], b[5];
#pragma unroll
            for (int i = 0; i < 4; i++) a[i] = As[kk][ty * 4 + i];
#pragma unroll
            for (int j = 0; j < 5; j++) b[j] = Bs[kk][tx * 5 + j];
#pragma unroll
            for (int i = 0; i < 4; i++)
#pragma unroll
                for (int j = 0; j < 5; j++) acc[i][j] += a[i] * b[j];
        }
        __syncthreads();
    }
#pragma unroll
    for (int i = 0; i < 4; i++) {
        int grow = row0 + ty * 4 + i;
        if (grow < NN) {
#pragma unroll
            for (int j = 0; j < 5; j++) g_h2[grow * 40 + tx * 5 + j] = acc[i][j];
        }
    }
}

// ---------------- per-node attention logits, layer 2 (warp/node) ----------------
__global__ void k_att2(const float* __restrict__ att_src, const float* __restrict__ att_dst) {
    int lane = threadIdx.x & 31;
    int warp = (blockIdx.x * blockDim.x + threadIdx.x) >> 5;
    int nwarp = (gridDim.x * blockDim.x) >> 5;
    float4 ws = make_float4(0.f, 0.f, 0.f, 0.f), wd = ws;
    if (lane < 10) {
        ws = *(const float4*)&att_src[lane * 4];
        wd = *(const float4*)&att_dst[lane * 4];
    }
    for (int n = warp; n < NN; n += nwarp) {
        float ps = 0.f, pd = 0.f;
        if (lane < 10) {
            float4 h = *(const float4*)&g_h2[n * 40 + lane * 4];
            ps = h.x * ws.x + h.y * ws.y + h.z * ws.z + h.w * ws.w;
            pd = h.x * wd.x + h.y * wd.y + h.z * wd.z + h.w * wd.w;
        }
#pragma unroll
        for (int o = 16; o > 0; o >>= 1) {
            ps += __shfl_xor_sync(0xffffffffu, ps, o);
            pd += __shfl_xor_sync(0xffffffffu, pd, o);
        }
        if (lane == 0) { g_as2[n] = ps; g_ad2[n] = pd; }
    }
}

// ---------------- layer2 edge passes ----------------
__global__ void k_e2max(const int* __restrict__ ei) {
    int e = blockIdx.x * blockDim.x + threadIdx.x;
    if (e >= NE) return;
    int s = ei[e], d = ei[NE + e];
    atomicMaxFloat(&g_max2[d], leaky(g_as2[s] + g_ad2[d]));
}

__global__ void k_e2sum(const int* __restrict__ ei) {
    int e = blockIdx.x * blockDim.x + threadIdx.x;
    if (e >= NE) return;
    int s = ei[e], d = ei[NE + e];
    float v = __expf(leaky(g_as2[s] + g_ad2[d]) - g_max2[d]);
    g_e2[e] = v;
    atomicAdd(&g_sum2[d], v);
}

__global__ void k_e2agg(const int* __restrict__ ei, float* __restrict__ dout) {
    const int total = NE * 10;
    int st = gridDim.x * blockDim.x;
    for (int t = blockIdx.x * blockDim.x + threadIdx.x; t < total; t += st) {
        int e = t / 10;
        int q = t % 10;
        int s = ei[e], d = ei[NE + e];
        float coef = g_e2[e] / g_sum2[d];
        float4 h = *(const float4*)&g_h2[s * 40 + q * 4];
        redAddV4(&dout[d * 40 + q * 4],
                 make_float4(h.x * coef, h.y * coef, h.z * coef, h.w * coef));
    }
}

// ---------------- launch ----------------
extern "C" void kernel_launch(void* const* d_in, const int* in_sizes, int n_in,
                              void* d_out, int out_size) {
    const float* x   = (const float*)d_in[0];
    const int*   ei  = (const int*)d_in[1];
    const float* W1  = (const float*)d_in[2];
    const float* as1 = (const float*)d_in[3];
    const float* ad1 = (const float*)d_in[4];
    const float* b1  = (const float*)d_in[5];
    const float* W2  = (const float*)d_in[6];
    const float* as2 = (const float*)d_in[7];
    const float* ad2 = (const float*)d_in[8];
    const float* b2  = (const float*)d_in[9];
    float* out = (float*)d_out;

    k_init<<<2048, 256>>>(b2, out);
    k_gemm1<<<(NN + 63) / 64, 256>>>(x, W1);
    k_att1<<<512, 256>>>(as1, ad1);
    k_e1max<<<(NE + 255) / 256, 256>>>(ei);
    k_e1sum<<<(NE + 255) / 256, 256>>>(ei);
    k_e1agg<<<(NE * 32 + 255) / 256, 256>>>(ei);
    k_act1<<<4096, 256>>>(b1);
    k_gemm2<<<(NN + 127) / 128, 256>>>(W2);
    k_att2<<<512, 256>>>(as2, ad2);
    k_e2max<<<(NE + 255) / 256, 256>>>(ei);
    k_e2sum<<<(NE + 255) / 256, 256>>>(ei);
    k_e2agg<<<(NE * 10 + 255) / 256, 256>>>(ei, out);
}

// round 2
// speedup vs baseline: 1.6775x; 1.6775x over previous
#include <cuda_runtime.h>
#include <math_constants.h>

#define NN 50000
#define NE 800000
#define HEADS 8
#define HID 16
#define H1DIM 128
#define OUTC 40
#define NEG 0.2f

// ---------------- scratch (allocation-free: __device__ globals) ----------------
__device__ float g_h1[NN * H1DIM];     // layer1 linear output
__device__ float g_as1[NN * HEADS];
__device__ float g_ad1[NN * HEADS];
__device__ float g_out1[NN * H1DIM];   // layer1 aggregated + ELU
__device__ float g_h2[NN * OUTC];
__device__ float g_as2[NN];
__device__ float g_ad2[NN];
__device__ int   g_deg[NN];
__device__ int   g_cur[NN];
__device__ int   g_off[NN + 1];
__device__ int   g_csrc[NE];           // CSR: src node per (dst-bucketed) edge

__device__ __forceinline__ float leaky(float v) { return v > 0.f ? v : NEG * v; }

// ---------------- init ----------------
__global__ void k_init() {
    int i = blockIdx.x * blockDim.x + threadIdx.x;
    int st = gridDim.x * blockDim.x;
    for (int j = i; j < NN; j += st) { g_deg[j] = 0; g_cur[j] = 0; }
}

// ---------------- CSR build ----------------
__global__ void k_deg(const int* __restrict__ ei) {
    int e = blockIdx.x * blockDim.x + threadIdx.x;
    if (e < NE) atomicAdd(&g_deg[ei[NE + e]], 1);
}

__global__ void k_scan() {   // single block, 1024 threads
    __shared__ int sums[1024];
    int t = threadIdx.x;
    const int CH = (NN + 1023) / 1024;   // 49
    int base = t * CH;
    int local = 0;
    for (int j = 0; j < CH; j++) {
        int idx = base + j;
        if (idx < NN) local += g_deg[idx];
    }
    sums[t] = local;
    __syncthreads();
    for (int o = 1; o < 1024; o <<= 1) {
        int v = (t >= o) ? sums[t - o] : 0;
        __syncthreads();
        sums[t] += v;
        __syncthreads();
    }
    int run = (t > 0) ? sums[t - 1] : 0;
    for (int j = 0; j < CH; j++) {
        int idx = base + j;
        if (idx < NN) { g_off[idx] = run; run += g_deg[idx]; }
    }
    if (t == 1023) g_off[NN] = sums[1023];
}

__global__ void k_scatter(const int* __restrict__ ei) {
    int e = blockIdx.x * blockDim.x + threadIdx.x;
    if (e >= NE) return;
    int s = ei[e], d = ei[NE + e];
    int pos = g_off[d] + atomicAdd(&g_cur[d], 1);
    g_csrc[pos] = s;
}

// ---------------- GEMM1: g_h1 = x @ W1, fused attention-logit epilogue ----------
// BM=64, BN=128, BK=16, 256 threads, TM=8, TN=4
__global__ void k_gemm1(const float* __restrict__ A, const float* __restrict__ B,
                        const float* __restrict__ att_src, const float* __restrict__ att_dst) {
    __shared__ float As[16][64];
    __shared__ float Bs[16][128];
    int tid = threadIdx.x;
    int tx = tid & 31;
    int ty = tid >> 5;
    int row0 = blockIdx.x * 64;
    float acc[8][4] = {};
    for (int k0 = 0; k0 < 128; k0 += 16) {
        {
            int r = tid >> 2;
            int kk = (tid & 3) * 4;
            int grow = row0 + r;
            float4 v = make_float4(0.f, 0.f, 0.f, 0.f);
            if (grow < NN) v = *(const float4*)&A[grow * 128 + k0 + kk];
            As[kk + 0][r] = v.x; As[kk + 1][r] = v.y;
            As[kk + 2][r] = v.z; As[kk + 3][r] = v.w;
        }
#pragma unroll
        for (int p = 0; p < 2; p++) {
            int fi = tid + p * 256;
            int kk = fi >> 5;
            int nc = (fi & 31) * 4;
            *(float4*)&Bs[kk][nc] = *(const float4*)&B[(k0 + kk) * 128 + nc];
        }
        __syncthreads();
#pragma unroll
        for (int kk = 0; kk < 16; kk++) {
            float a[8], b[4];
#pragma unroll
            for (int i = 0; i < 8; i++) a[i] = As[kk][ty * 8 + i];
#pragma unroll
            for (int j = 0; j < 4; j++) b[j] = Bs[kk][tx * 4 + j];
#pragma unroll
            for (int i = 0; i < 8; i++)
#pragma unroll
                for (int j = 0; j < 4; j++) acc[i][j] += a[i] * b[j];
        }
        __syncthreads();
    }
    float4 ws = *(const float4*)&att_src[tx * 4];
    float4 wd = *(const float4*)&att_dst[tx * 4];
#pragma unroll
    for (int i = 0; i < 8; i++) {
        int grow = row0 + ty * 8 + i;
        if (grow < NN)
            *(float4*)&g_h1[grow * 128 + tx * 4] =
                make_float4(acc[i][0], acc[i][1], acc[i][2], acc[i][3]);
        // fused per-head logits: head = tx>>2 (cols tx*4..+4 lie inside one head)
        float ps = acc[i][0] * ws.x + acc[i][1] * ws.y + acc[i][2] * ws.z + acc[i][3] * ws.w;
        float pd = acc[i][0] * wd.x + acc[i][1] * wd.y + acc[i][2] * wd.z + acc[i][3] * wd.w;
        ps += __shfl_xor_sync(0xffffffffu, ps, 1);
        ps += __shfl_xor_sync(0xffffffffu, ps, 2);
        pd += __shfl_xor_sync(0xffffffffu, pd, 1);
        pd += __shfl_xor_sync(0xffffffffu, pd, 2);
        if ((tx & 3) == 0 && grow < NN) {
            g_as1[grow * 8 + (tx >> 2)] = ps;
            g_ad1[grow * 8 + (tx >> 2)] = pd;
        }
    }
}

// ---------------- layer1: per-node softmax + aggregation + bias + ELU -----------
// one warp per dst node; lane handles channels [lane*4, lane*4+4), head = lane>>2
__global__ void k_node1(const float* __restrict__ b1) {
    int lane = threadIdx.x & 31;
    int warp = (blockIdx.x * blockDim.x + threadIdx.x) >> 5;
    int nwarp = (gridDim.x * blockDim.x) >> 5;
    int h = lane >> 2;
    for (int n = warp; n < NN; n += nwarp) {
        int beg = g_off[n], end = g_off[n + 1];
        float ad = g_ad1[n * 8 + h];
        // pass 1: per-head max (quad-partitioned over edges)
        float mx = -CUDART_INF_F;
        for (int i = beg + (lane & 3); i < end; i += 4) {
            int s = g_csrc[i];
            mx = fmaxf(mx, leaky(g_as1[s * 8 + h] + ad));
        }
        mx = fmaxf(mx, __shfl_xor_sync(0xffffffffu, mx, 1));
        mx = fmaxf(mx, __shfl_xor_sync(0xffffffffu, mx, 2));
        // pass 2: weighted accumulation
        float4 acc = make_float4(0.f, 0.f, 0.f, 0.f);
        float sum = 0.f;
        for (int i = beg; i < end; i++) {
            int s = g_csrc[i];
            float e = __expf(leaky(g_as1[s * 8 + h] + ad) - mx);
            sum += e;
            float4 hv = *(const float4*)&g_h1[s * 128 + lane * 4];
            acc.x += e * hv.x; acc.y += e * hv.y;
            acc.z += e * hv.z; acc.w += e * hv.w;
        }
        float inv = (sum > 0.f) ? 1.f / sum : 0.f;
        float4 bv = *(const float4*)&b1[lane * 4];
        float4 o;
        o.x = acc.x * inv + bv.x; o.y = acc.y * inv + bv.y;
        o.z = acc.z * inv + bv.z; o.w = acc.w * inv + bv.w;
        o.x = o.x > 0.f ? o.x : expm1f(o.x);
        o.y = o.y > 0.f ? o.y : expm1f(o.y);
        o.z = o.z > 0.f ? o.z : expm1f(o.z);
        o.w = o.w > 0.f ? o.w : expm1f(o.w);
        *(float4*)&g_out1[n * 128 + lane * 4] = o;
    }
}

// ---------------- GEMM2: g_h2 = g_out1 @ W2, fused attention-logit epilogue -----
// BM=128, BK=16, 256 threads, TM=4, TN=5
__global__ void k_gemm2(const float* __restrict__ B,
                        const float* __restrict__ att_src, const float* __restrict__ att_dst) {
    __shared__ float As[16][128];
    __shared__ float Bs[16][40];
    int tid = threadIdx.x;
    int tx = tid & 7;
    int ty = tid >> 3;
    int row0 = blockIdx.x * 128;
    float acc[4][5] = {};
    for (int k0 = 0; k0 < 128; k0 += 16) {
#pragma unroll
        for (int p = 0; p < 2; p++) {
            int fi = tid + p * 256;
            int r = fi >> 2;
            int kk = (fi & 3) * 4;
            int grow = row0 + r;
            float4 v = make_float4(0.f, 0.f, 0.f, 0.f);
            if (grow < NN) v = *(const float4*)&g_out1[grow * 128 + k0 + kk];
            As[kk + 0][r] = v.x; As[kk + 1][r] = v.y;
            As[kk + 2][r] = v.z; As[kk + 3][r] = v.w;
        }
        if (tid < 160) {
            int kk = tid / 10;
            int nc = (tid % 10) * 4;
            *(float4*)&Bs[kk][nc] = *(const float4*)&B[(k0 + kk) * 40 + nc];
        }
        __syncthreads();
#pragma unroll
        for (int kk = 0; kk < 16; kk++) {
            float a[4], b[5];
#pragma unroll
            for (int i = 0; i < 4; i++) a[i] = As[kk][ty * 4 + i];
#pragma unroll
            for (int j = 0; j < 5; j++) b[j] = Bs[kk][tx * 5 + j];
#pragma unroll
            for (int i = 0; i < 4; i++)
#pragma unroll
                for (int j = 0; j < 5; j++) acc[i][j] += a[i] * b[j];
        }
        __syncthreads();
    }
    float ws[5], wd[5];
#pragma unroll
    for (int j = 0; j < 5; j++) { ws[j] = att_src[tx * 5 + j]; wd[j] = att_dst[tx * 5 + j]; }
#pragma unroll
    for (int i = 0; i < 4; i++) {
        int grow = row0 + ty * 4 + i;
        float ps = 0.f, pd = 0.f;
#pragma unroll
        for (int j = 0; j < 5; j++) {
            ps += acc[i][j] * ws[j];
            pd += acc[i][j] * wd[j];
            if (grow < NN) g_h2[grow * 40 + tx * 5 + j] = acc[i][j];
        }
        ps += __shfl_xor_sync(0xffffffffu, ps, 1);
        ps += __shfl_xor_sync(0xffffffffu, ps, 2);
        ps += __shfl_xor_sync(0xffffffffu, ps, 4);
        pd += __shfl_xor_sync(0xffffffffu, pd, 1);
        pd += __shfl_xor_sync(0xffffffffu, pd, 2);
        pd += __shfl_xor_sync(0xffffffffu, pd, 4);
        if (tx == 0 && grow < NN) { g_as2[grow] = ps; g_ad2[grow] = pd; }
    }
}

// ---------------- layer2: per-node softmax + aggregation + bias → d_out ---------
__global__ void k_node2(const float* __restrict__ b2, float* __restrict__ dout) {
    int lane = threadIdx.x & 31;
    int warp = (blockIdx.x * blockDim.x + threadIdx.x) >> 5;
    int nwarp = (gridDim.x * blockDim.x) >> 5;
    for (int n = warp; n < NN; n += nwarp) {
        int beg = g_off[n], end = g_off[n + 1];
        float ad = g_ad2[n];
        float mx = -CUDART_INF_F;
        for (int i = beg + lane; i < end; i += 32) {
            int s = g_csrc[i];
            mx = fmaxf(mx, leaky(g_as2[s] + ad));
        }
#pragma unroll
        for (int o = 16; o > 0; o >>= 1)
            mx = fmaxf(mx, __shfl_xor_sync(0xffffffffu, mx, o));
        float4 acc = make_float4(0.f, 0.f, 0.f, 0.f);
        float sum = 0.f;
        for (int i = beg; i < end; i++) {
            int s = g_csrc[i];
            float e = __expf(leaky(g_as2[s] + ad) - mx);
            sum += e;
            if (lane < 10) {
                float4 hv = *(const float4*)&g_h2[s * 40 + lane * 4];
                acc.x += e * hv.x; acc.y += e * hv.y;
                acc.z += e * hv.z; acc.w += e * hv.w;
            }
        }
        float inv = (sum > 0.f) ? 1.f / sum : 0.f;
        if (lane < 10) {
            float4 bv = *(const float4*)&b2[lane * 4];
            float4 o;
            o.x = acc.x * inv + bv.x; o.y = acc.y * inv + bv.y;
            o.z = acc.z * inv + bv.z; o.w = acc.w * inv + bv.w;
            *(float4*)&dout[n * 40 + lane * 4] = o;
        }
    }
}

// ---------------- launch ----------------
extern "C" void kernel_launch(void* const* d_in, const int* in_sizes, int n_in,
                              void* d_out, int out_size) {
    const float* x   = (const float*)d_in[0];
    const int*   ei  = (const int*)d_in[1];
    const float* W1  = (const float*)d_in[2];
    const float* as1 = (const float*)d_in[3];
    const float* ad1 = (const float*)d_in[4];
    const float* b1  = (const float*)d_in[5];
    const float* W2  = (const float*)d_in[6];
    const float* as2 = (const float*)d_in[7];
    const float* ad2 = (const float*)d_in[8];
    const float* b2  = (const float*)d_in[9];
    float* out = (float*)d_out;

    k_init<<<128, 256>>>();
    k_deg<<<(NE + 255) / 256, 256>>>(ei);
    k_scan<<<1, 1024>>>();
    k_scatter<<<(NE + 255) / 256, 256>>>(ei);
    k_gemm1<<<(NN + 63) / 64, 256>>>(x, W1, as1, ad1);
    k_node1<<<(NN * 32 + 255) / 256, 256>>>(b1);
    k_gemm2<<<(NN + 127) / 128, 256>>>(W2, as2, ad2);
    k_node2<<<(NN * 32 + 255) / 256, 256>>>(b2, out);
}